// round 11
// baseline (speedup 1.0000x reference)
#include <cuda_runtime.h>

#define HOP    256
#define NB     128
#define TFR    1001
#define LOUT   256000
#define NPAIR  501            // ceil(1001/2)

// ---- packed f32x2 ops (Blackwell) ----
__device__ __forceinline__ float2 padd(float2 a, float2 b) {
    float2 r;
    asm("add.rn.f32x2 %0, %1, %2;"
        : "=l"(reinterpret_cast<unsigned long long&>(r))
        : "l"(reinterpret_cast<unsigned long long&>(a)),
          "l"(reinterpret_cast<unsigned long long&>(b)));
    return r;
}
__device__ __forceinline__ float2 psub(float2 a, float2 b) {
    float2 r;
    asm("sub.rn.f32x2 %0, %1, %2;"
        : "=l"(reinterpret_cast<unsigned long long&>(r))
        : "l"(reinterpret_cast<unsigned long long&>(a)),
          "l"(reinterpret_cast<unsigned long long&>(b)));
    return r;
}
__device__ __forceinline__ float2 cmul(float2 a, float2 b) {
    return make_float2(fmaf(a.x, b.x, -a.y * b.y), fmaf(a.x, b.y, a.y * b.x));
}

// Output permutation of the local 32-pt DIF FFT (radix 4,4,2):
// position p = 8a + 2b + c  holds bin  k = a + 4b + 16c
__host__ __device__ constexpr int SIG(int p)  { return (p >> 3) + 4 * ((p >> 1) & 3) + 16 * (p & 1); }
__host__ __device__ constexpr int ISIG(int k) { return 8 * (k & 3) + 2 * ((k >> 2) & 3) + (k >> 4); }
__host__ __device__ constexpr int MIDX(int P, int i) { return P ? ISIG(i) : i; }

// W_32^k constants, k = 0..21 : (cos(2pi k/32), -sin(2pi k/32))
__device__ __constant__ const float W32R[22] = {
    1.0f, 0.98078528f, 0.92387953f, 0.83146961f, 0.70710678f, 0.55557023f,
    0.38268343f, 0.19509032f, 0.0f, -0.19509032f, -0.38268343f, -0.55557023f,
    -0.70710678f, -0.83146961f, -0.92387953f, -0.98078528f, -1.0f,
    -0.98078528f, -0.92387953f, -0.83146961f, -0.70710678f, -0.55557023f };
__device__ __constant__ const float W32I[22] = {
    0.0f, -0.19509032f, -0.38268343f, -0.55557023f, -0.70710678f, -0.83146961f,
    -0.92387953f, -0.98078528f, -1.0f, -0.98078528f, -0.92387953f, -0.83146961f,
    -0.70710678f, -0.55557023f, -0.38268343f, -0.19509032f, 0.0f,
    0.19509032f, 0.38268343f, 0.55557023f, 0.70710678f, 0.83146961f };

__device__ __forceinline__ void bf_dif3(float2& a, float2& b, float2& c, float2& d,
                                        float2 w1, float2 w2, float2 w3) {
    float2 t0 = padd(a, c), t1 = psub(a, c), t2 = padd(b, d);
    float2 t3 = make_float2(b.y - d.y, d.x - b.x);   // -i*(b-d)
    a = padd(t0, t2);
    float2 o1 = padd(t1, t3), o2 = psub(t0, t2), o3 = psub(t1, t3);
    b = cmul(o1, w1); c = cmul(o2, w2); d = cmul(o3, w3);
}
__device__ __forceinline__ void bf_dif_nt(float2& a, float2& b, float2& c, float2& d) {
    float2 t0 = padd(a, c), t1 = psub(a, c), t2 = padd(b, d);
    float2 t3 = make_float2(b.y - d.y, d.x - b.x);
    a = padd(t0, t2); b = padd(t1, t3); c = psub(t0, t2); d = psub(t1, t3);
}

// In-place 32-pt DIF FFT with compile-time register remap P.
template<int P>
__device__ __forceinline__ void fft32t(float2 v[32]) {
    bf_dif_nt(v[MIDX(P,0)], v[MIDX(P,8)], v[MIDX(P,16)], v[MIDX(P,24)]);
    #pragma unroll
    for (int i = 1; i < 8; i++)
        bf_dif3(v[MIDX(P,i)], v[MIDX(P,i+8)], v[MIDX(P,i+16)], v[MIDX(P,i+24)],
                make_float2(W32R[i], W32I[i]),
                make_float2(W32R[2 * i], W32I[2 * i]),
                make_float2(W32R[3 * i], W32I[3 * i]));
    #pragma unroll
    for (int blk = 0; blk < 4; blk++) {
        const int s = 8 * blk;
        bf_dif_nt(v[MIDX(P,s)], v[MIDX(P,s+2)], v[MIDX(P,s+4)], v[MIDX(P,s+6)]);
        bf_dif3(v[MIDX(P,s+1)], v[MIDX(P,s+3)], v[MIDX(P,s+5)], v[MIDX(P,s+7)],
                make_float2(W32R[4], W32I[4]),
                make_float2(W32R[8], W32I[8]),
                make_float2(W32R[12], W32I[12]));
    }
    #pragma unroll
    for (int u = 0; u < 16; u++) {
        float2 a = v[MIDX(P,2*u)], b = v[MIDX(P,2*u+1)];
        v[MIDX(P,2*u)]   = padd(a, b);
        v[MIDX(P,2*u+1)] = psub(a, b);
    }
}

// Multiply logical slot ISIG(m) (bin k1=m) by W_1024^{lane*m}; base A1 = W_1024^lane.
template<int P>
__device__ __forceinline__ void twmult(float2 v[32], float2 A1) {
    float2 A2 = cmul(A1, A1);
    float2 A4 = cmul(A2, A2);
    float2 B8  = cmul(A4, A4);
    float2 B16 = cmul(B8, B8);
    float2 B24 = cmul(B16, B8);
    v[MIDX(P,ISIG(8))]  = cmul(v[MIDX(P,ISIG(8))],  B8);
    v[MIDX(P,ISIG(16))] = cmul(v[MIDX(P,ISIG(16))], B16);
    v[MIDX(P,ISIG(24))] = cmul(v[MIDX(P,ISIG(24))], B24);
    float2 A = A1;
    #pragma unroll
    for (int d = 1; d < 8; d++) {
        v[MIDX(P,ISIG(d))]      = cmul(v[MIDX(P,ISIG(d))],      A);
        v[MIDX(P,ISIG(8 + d))]  = cmul(v[MIDX(P,ISIG(8 + d))],  cmul(B8,  A));
        v[MIDX(P,ISIG(16 + d))] = cmul(v[MIDX(P,ISIG(16 + d))], cmul(B16, A));
        v[MIDX(P,ISIG(24 + d))] = cmul(v[MIDX(P,ISIG(24 + d))], cmul(B24, A));
        if (d < 7) A = cmul(A, A1);
    }
}

// W[k] = gp*Zk + gm*conj(Zm); returns conj(W)
__device__ __forceinline__ float2 combW(float g0, float g1, float2 Zk, float2 Zm) {
    float gp = 0.5f * (g0 + g1), gm = 0.5f * (g0 - g1);
    return make_float2(fmaf(gp, Zk.x, gm * Zm.x),
                       fmaf(-gp, Zk.y, gm * Zm.y));
}

__device__ __forceinline__ float2 shfl2(float2 v, int src) {
    float2 r;
    r.x = __shfl_sync(0xffffffffu, v.x, src);
    r.y = __shfl_sync(0xffffffffu, v.y, src);
    return r;
}

// INTERIOR=true: unguarded loads/stores, pr = 1 + 4*bx + wid (pairs 1..498)
// INTERIOR=false: guarded, pr = {0,499,500} by warp (single block per batch)
template<bool INTERIOR>
__global__ void __launch_bounds__(128, INTERIOR ? 5 : 1)
filtered_noise_kernel(const float* __restrict__ fb,     // (16,1,128,1001)
                      const float* __restrict__ noise,  // (16,1,256000)
                      float* __restrict__ out)          // (16,1,256000)
{
    __shared__ float2 tb[4][33 * 32];   // per-warp transpose buffer (33-stride pad)
    __shared__ float2 FP[4][NB];        // per-warp (g0,g1) band gains
    __shared__ float  wint[1024];       // Hann * (1/1024)

    const int tid  = threadIdx.x;
    const int wid  = tid >> 5;
    const int lane = tid & 31;
    const int b    = blockIdx.y;

    int pr;
    if (INTERIOR) {
        pr = 1 + blockIdx.x * 4 + wid;
    } else {
        const int bmap[4] = {0, 499, 500, -1};
        pr = bmap[wid];
    }

    #pragma unroll
    for (int idx = tid; idx < 1024; idx += 128)
        wint[idx] = 0.5f * (1.0f - cospif((float)(2 * idx) * (1.0f / 1023.0f)))
                  * (1.0f / 1024.0f);
    __syncthreads();
    if (INTERIOR) { if (pr > 498) return; }
    else          { if (pr < 0)  return; }

    const int  t0 = 2 * pr;
    const bool v1 = INTERIOR ? true : ((t0 + 1) < TFR);

    float2* FPw = FP[wid];
    #pragma unroll
    for (int u = lane; u < NB; u += 32) {
        float g0 = fb[(b * NB + u) * TFR + t0];
        float g1 = v1 ? fb[(b * NB + u) * TFR + t0 + 1] : 0.0f;
        FPw[u] = make_float2(g0, g1);
    }

    float2* tbw = tb[wid];
    const int    base0 = t0 * HOP - 512;
    const size_t nOff  = (size_t)b * LOUT;
    float2 A1;
    {
        float sn, cs;
        sincospif(-(float)lane * (1.0f / 512.0f), &sn, &cs);
        A1 = make_float2(cs, sn);
    }

    // ---- load: v[n1] = z[32*n1 + lane], z = frame(t0) + i*frame(t1) ----
    float2 v[32];
    if (INTERIOR) {
        const float* np = noise + nOff + base0 + lane;
        #pragma unroll
        for (int n1 = 0; n1 < 32; n1++) {
            float xa = np[32 * n1];
            float xb = np[32 * n1 + HOP];
            v[n1] = make_float2(fmaf(xa, 2.0f, -1.0f), fmaf(xb, 2.0f, -1.0f));
        }
    } else {
        #pragma unroll
        for (int n1 = 0; n1 < 32; n1++) {
            int s0 = base0 + 32 * n1 + lane;
            int s1 = s0 + HOP;
            float xa = (s0 >= 0 && s0 < LOUT) ? fmaf(noise[nOff + s0], 2.0f, -1.0f) : 0.0f;
            float xb = (v1 && s1 >= 0 && s1 < LOUT) ? fmaf(noise[nOff + s1], 2.0f, -1.0f) : 0.0f;
            v[n1] = make_float2(xa, xb);
        }
    }

    // ================= forward four-step FFT =================
    fft32t<0>(v);             // over n1; reg p holds k1 = SIG(p)
    twmult<0>(v, A1);         // *= W_1024^{lane * k1}
    #pragma unroll
    for (int p = 0; p < 32; p++) tbw[33 * SIG(p) + lane] = v[p];
    __syncwarp();
    #pragma unroll
    for (int n2 = 0; n2 < 32; n2++) v[n2] = tbw[33 * lane + n2];
    fft32t<0>(v);             // reg q holds bin k = 32*SIG(q) + lane

    // ================= spectral combine, IN PLACE (bin-indexed regs) =================
    {
        const int pl = (32 - lane) & 31;
        #pragma unroll
        for (int sq = 0; sq < 16; sq++) {
            const int q = ISIG(sq), tq = ISIG(31 - sq);
            float2 pq  = shfl2(v[tq], pl);   // partner value for bin at reg q
            float2 ptq = shfl2(v[q],  pl);   // partner value for bin at reg tq
            if (lane != 0) {
                float2 gq  = FPw[(32 * sq + lane - 1) >> 2];
                float2 gtq = FPw[(32 * sq + 31 - lane) >> 2];
                float2 nq  = combW(gq.x,  gq.y,  v[q],  pq);
                float2 ntq = combW(gtq.x, gtq.y, v[tq], ptq);
                v[q]  = nq;
                v[tq] = ntq;
            }
        }
        if (lane == 0) {
            #pragma unroll
            for (int sq = 1; sq < 16; sq++) {
                const int qa = ISIG(sq), qb = ISIG(32 - sq);
                float2 A = v[qa], B = v[qb];
                float2 g = FPw[(32 * sq - 1) >> 2];
                v[qa] = combW(g.x, g.y, A, B);
                v[qb] = combW(g.x, g.y, B, A);
            }
            float2 g512 = FPw[127];
            v[ISIG(16)] = combW(g512.x, g512.y, v[ISIG(16)], v[ISIG(16)]);
            v[0] = make_float2(0.0f, 0.0f);   // DC (reg ISIG(0) = 0)
        }
    }

    // ================= inverse four-step (forward FFT of conj spectrum) =================
    fft32t<1>(v);
    twmult<1>(v, A1);
    __syncwarp();             // WAR: forward transpose reads done in all lanes
    #pragma unroll
    for (int p = 0; p < 32; p++) tbw[33 * SIG(p) + lane] = v[MIDX(1, p)];
    __syncwarp();
    #pragma unroll
    for (int n2 = 0; n2 < 32; n2++) v[n2] = tbw[33 * lane + n2];
    fft32t<0>(v);             // reg q: time sample n = 32*SIG(q) + lane (x1024, conj)

    // ---- Hann window + FUSED overlap-add (40 atomics) ----
    const float* wp = wint + lane;
    if (INTERIOR) {
        float* op = out + nOff + base0 + lane;
        #pragma unroll
        for (int h = 0; h < 40; h++) {
            float acc;
            if (h < 8)
                acc = v[ISIG(h)].x * wp[32 * h];
            else if (h < 32)
                acc = fmaf(v[ISIG(h)].x, wp[32 * h],
                           -v[ISIG(h - 8)].y * wp[32 * (h - 8)]);
            else
                acc = -v[ISIG(h - 8)].y * wp[32 * (h - 8)];
            atomicAdd(&op[32 * h], acc);
        }
    } else {
        #pragma unroll
        for (int h = 0; h < 40; h++) {
            float acc = 0.0f;
            if (h < 32)
                acc = v[ISIG(h)].x * wp[32 * h];
            if (h >= 8 && v1)
                acc += -v[ISIG(h - 8)].y * wp[32 * (h - 8)];
            int s = base0 + 32 * h + lane;
            if (s >= 0 && s < LOUT)
                atomicAdd(&out[nOff + s], acc);
        }
    }
}

extern "C" void kernel_launch(void* const* d_in, const int* in_sizes, int n_in,
                              void* d_out, int out_size)
{
    const float* fb    = (const float*)d_in[0];
    const float* noise = (const float*)d_in[1];
    float* out = (float*)d_out;

    cudaMemsetAsync(out, 0, (size_t)out_size * sizeof(float));

    // interior pairs 1..498 : 125 blocks x 4 warps (2 idle slots)
    filtered_noise_kernel<true><<<dim3(125, 16), 128>>>(fb, noise, out);
    // boundary pairs {0, 499, 500}
    filtered_noise_kernel<false><<<dim3(1, 16), 128>>>(fb, noise, out);
}

// round 12
// speedup vs baseline: 1.0013x; 1.0013x over previous
#include <cuda_runtime.h>

#define HOP    256
#define NB     128
#define TFR    1001
#define LOUT   256000
#define NPAIR  501            // ceil(1001/2)

// ---- packed f32x2 ops (Blackwell) ----
__device__ __forceinline__ float2 padd(float2 a, float2 b) {
    float2 r;
    asm("add.rn.f32x2 %0, %1, %2;"
        : "=l"(reinterpret_cast<unsigned long long&>(r))
        : "l"(reinterpret_cast<unsigned long long&>(a)),
          "l"(reinterpret_cast<unsigned long long&>(b)));
    return r;
}
__device__ __forceinline__ float2 psub(float2 a, float2 b) {
    float2 r;
    asm("sub.rn.f32x2 %0, %1, %2;"
        : "=l"(reinterpret_cast<unsigned long long&>(r))
        : "l"(reinterpret_cast<unsigned long long&>(a)),
          "l"(reinterpret_cast<unsigned long long&>(b)));
    return r;
}
__device__ __forceinline__ float2 cmul(float2 a, float2 b) {
    return make_float2(fmaf(a.x, b.x, -a.y * b.y), fmaf(a.x, b.y, a.y * b.x));
}

// Output permutation of the local 32-pt DIF FFT (radix 4,4,2):
// position p = 8a + 2b + c  holds bin  k = a + 4b + 16c
__host__ __device__ constexpr int SIG(int p)  { return (p >> 3) + 4 * ((p >> 1) & 3) + 16 * (p & 1); }
__host__ __device__ constexpr int ISIG(int k) { return 8 * (k & 3) + 2 * ((k >> 2) & 3) + (k >> 4); }
__host__ __device__ constexpr int MIDX(int P, int i) { return P ? ISIG(i) : i; }

// W_32^k constants, k = 0..21 : (cos(2pi k/32), -sin(2pi k/32))
__device__ __constant__ const float W32R[22] = {
    1.0f, 0.98078528f, 0.92387953f, 0.83146961f, 0.70710678f, 0.55557023f,
    0.38268343f, 0.19509032f, 0.0f, -0.19509032f, -0.38268343f, -0.55557023f,
    -0.70710678f, -0.83146961f, -0.92387953f, -0.98078528f, -1.0f,
    -0.98078528f, -0.92387953f, -0.83146961f, -0.70710678f, -0.55557023f };
__device__ __constant__ const float W32I[22] = {
    0.0f, -0.19509032f, -0.38268343f, -0.55557023f, -0.70710678f, -0.83146961f,
    -0.92387953f, -0.98078528f, -1.0f, -0.98078528f, -0.92387953f, -0.83146961f,
    -0.70710678f, -0.55557023f, -0.38268343f, -0.19509032f, 0.0f,
    0.19509032f, 0.38268343f, 0.55557023f, 0.70710678f, 0.83146961f };

__device__ __forceinline__ void bf_dif3(float2& a, float2& b, float2& c, float2& d,
                                        float2 w1, float2 w2, float2 w3) {
    float2 t0 = padd(a, c), t1 = psub(a, c), t2 = padd(b, d);
    float2 t3 = make_float2(b.y - d.y, d.x - b.x);   // -i*(b-d)
    a = padd(t0, t2);
    float2 o1 = padd(t1, t3), o2 = psub(t0, t2), o3 = psub(t1, t3);
    b = cmul(o1, w1); c = cmul(o2, w2); d = cmul(o3, w3);
}
__device__ __forceinline__ void bf_dif_nt(float2& a, float2& b, float2& c, float2& d) {
    float2 t0 = padd(a, c), t1 = psub(a, c), t2 = padd(b, d);
    float2 t3 = make_float2(b.y - d.y, d.x - b.x);
    a = padd(t0, t2); b = padd(t1, t3); c = psub(t0, t2); d = psub(t1, t3);
}

// In-place 32-pt DIF FFT with compile-time register remap P.
template<int P>
__device__ __forceinline__ void fft32t(float2 v[32]) {
    bf_dif_nt(v[MIDX(P,0)], v[MIDX(P,8)], v[MIDX(P,16)], v[MIDX(P,24)]);
    #pragma unroll
    for (int i = 1; i < 8; i++)
        bf_dif3(v[MIDX(P,i)], v[MIDX(P,i+8)], v[MIDX(P,i+16)], v[MIDX(P,i+24)],
                make_float2(W32R[i], W32I[i]),
                make_float2(W32R[2 * i], W32I[2 * i]),
                make_float2(W32R[3 * i], W32I[3 * i]));
    #pragma unroll
    for (int blk = 0; blk < 4; blk++) {
        const int s = 8 * blk;
        bf_dif_nt(v[MIDX(P,s)], v[MIDX(P,s+2)], v[MIDX(P,s+4)], v[MIDX(P,s+6)]);
        bf_dif3(v[MIDX(P,s+1)], v[MIDX(P,s+3)], v[MIDX(P,s+5)], v[MIDX(P,s+7)],
                make_float2(W32R[4], W32I[4]),
                make_float2(W32R[8], W32I[8]),
                make_float2(W32R[12], W32I[12]));
    }
    #pragma unroll
    for (int u = 0; u < 16; u++) {
        float2 a = v[MIDX(P,2*u)], b = v[MIDX(P,2*u+1)];
        v[MIDX(P,2*u)]   = padd(a, b);
        v[MIDX(P,2*u+1)] = psub(a, b);
    }
}

// Multiply logical slot ISIG(m) (bin k1=m) by W_1024^{lane*m}; base A1 = W_1024^lane.
template<int P>
__device__ __forceinline__ void twmult(float2 v[32], float2 A1) {
    float2 A2 = cmul(A1, A1);
    float2 A4 = cmul(A2, A2);
    float2 B8  = cmul(A4, A4);
    float2 B16 = cmul(B8, B8);
    float2 B24 = cmul(B16, B8);
    v[MIDX(P,ISIG(8))]  = cmul(v[MIDX(P,ISIG(8))],  B8);
    v[MIDX(P,ISIG(16))] = cmul(v[MIDX(P,ISIG(16))], B16);
    v[MIDX(P,ISIG(24))] = cmul(v[MIDX(P,ISIG(24))], B24);
    float2 A = A1;
    #pragma unroll
    for (int d = 1; d < 8; d++) {
        v[MIDX(P,ISIG(d))]      = cmul(v[MIDX(P,ISIG(d))],      A);
        v[MIDX(P,ISIG(8 + d))]  = cmul(v[MIDX(P,ISIG(8 + d))],  cmul(B8,  A));
        v[MIDX(P,ISIG(16 + d))] = cmul(v[MIDX(P,ISIG(16 + d))], cmul(B16, A));
        v[MIDX(P,ISIG(24 + d))] = cmul(v[MIDX(P,ISIG(24 + d))], cmul(B24, A));
        if (d < 7) A = cmul(A, A1);
    }
}

// W[k] = gp*Zk + gm*conj(Zm); returns conj(W)
__device__ __forceinline__ float2 combW(float g0, float g1, float2 Zk, float2 Zm) {
    float gp = 0.5f * (g0 + g1), gm = 0.5f * (g0 - g1);
    return make_float2(fmaf(gp, Zk.x, gm * Zm.x),
                       fmaf(-gp, Zk.y, gm * Zm.y));
}

__device__ __forceinline__ float2 shfl2(float2 v, int src) {
    float2 r;
    r.x = __shfl_sync(0xffffffffu, v.x, src);
    r.y = __shfl_sync(0xffffffffu, v.y, src);
    return r;
}

// Single kernel, all 501 pairs, ONE code path with uniform cheap guards.
__global__ void __launch_bounds__(128, 5)
filtered_noise_kernel(const float* __restrict__ fb,     // (16,1,128,1001)
                      const float* __restrict__ noise,  // (16,1,256000)
                      float* __restrict__ out)          // (16,1,256000)
{
    __shared__ float2 tb[4][33 * 32];   // per-warp transpose buffer (33-stride pad)
    __shared__ float2 FP[4][NB];        // per-warp (g0,g1) band gains
    __shared__ float  wint[1024];       // Hann * (1/1024)

    const int tid  = threadIdx.x;
    const int wid  = tid >> 5;
    const int lane = tid & 31;
    const int b    = blockIdx.y;
    const int pr   = blockIdx.x * 4 + wid;

    #pragma unroll
    for (int idx = tid; idx < 1024; idx += 128)
        wint[idx] = 0.5f * (1.0f - cospif((float)(2 * idx) * (1.0f / 1023.0f)))
                  * (1.0f / 1024.0f);
    __syncthreads();
    if (pr >= NPAIR) return;

    const int  t0 = 2 * pr;
    const bool v1 = (t0 + 1) < TFR;    // uniform; guards only the fb gain load

    float2* FPw = FP[wid];
    #pragma unroll
    for (int u = lane; u < NB; u += 32) {
        float g0 = fb[(b * NB + u) * TFR + t0];
        float g1 = v1 ? fb[(b * NB + u) * TFR + t0 + 1] : 0.0f;
        FPw[u] = make_float2(g0, g1);
    }

    float2* tbw = tb[wid];
    const int    base0 = t0 * HOP - 512;
    const size_t nOff  = (size_t)b * LOUT;
    float2 A1;
    {
        float sn, cs;
        sincospif(-(float)lane * (1.0f / 512.0f), &sn, &cs);
        A1 = make_float2(cs, sn);
    }

    // ---- guarded load: v[n1] = z[32*n1 + lane], z = frame(t0) + i*frame(t1) ----
    // (pair 500's frame t1 reads in-range garbage-free zeros via predicates; its
    //  contribution is zeroed exactly by g1 = 0 through linearity)
    const float* np = noise + nOff;
    float2 v[32];
    #pragma unroll
    for (int n1 = 0; n1 < 32; n1++) {
        int s0 = base0 + 32 * n1 + lane;
        int s1 = s0 + HOP;
        float xa = ((unsigned)s0 < (unsigned)LOUT) ? fmaf(np[s0], 2.0f, -1.0f) : 0.0f;
        float xb = ((unsigned)s1 < (unsigned)LOUT) ? fmaf(np[s1], 2.0f, -1.0f) : 0.0f;
        v[n1] = make_float2(xa, xb);
    }

    // ================= forward four-step FFT =================
    fft32t<0>(v);             // over n1; reg p holds k1 = SIG(p)
    twmult<0>(v, A1);         // *= W_1024^{lane * k1}
    #pragma unroll
    for (int p = 0; p < 32; p++) tbw[33 * SIG(p) + lane] = v[p];
    __syncwarp();
    #pragma unroll
    for (int n2 = 0; n2 < 32; n2++) v[n2] = tbw[33 * lane + n2];
    fft32t<0>(v);             // reg q holds bin k = 32*SIG(q) + lane

    // ================= spectral combine, IN PLACE (bin-indexed regs) =================
    {
        const int pl = (32 - lane) & 31;
        #pragma unroll
        for (int sq = 0; sq < 16; sq++) {
            const int q = ISIG(sq), tq = ISIG(31 - sq);
            float2 pq  = shfl2(v[tq], pl);   // partner value for bin at reg q
            float2 ptq = shfl2(v[q],  pl);   // partner value for bin at reg tq
            if (lane != 0) {
                float2 gq  = FPw[(32 * sq + lane - 1) >> 2];
                float2 gtq = FPw[(32 * sq + 31 - lane) >> 2];
                float2 nq  = combW(gq.x,  gq.y,  v[q],  pq);
                float2 ntq = combW(gtq.x, gtq.y, v[tq], ptq);
                v[q]  = nq;
                v[tq] = ntq;
            }
        }
        if (lane == 0) {
            #pragma unroll
            for (int sq = 1; sq < 16; sq++) {
                const int qa = ISIG(sq), qb = ISIG(32 - sq);
                float2 A = v[qa], B = v[qb];
                float2 g = FPw[(32 * sq - 1) >> 2];
                v[qa] = combW(g.x, g.y, A, B);
                v[qb] = combW(g.x, g.y, B, A);
            }
            float2 g512 = FPw[127];
            v[ISIG(16)] = combW(g512.x, g512.y, v[ISIG(16)], v[ISIG(16)]);
            v[0] = make_float2(0.0f, 0.0f);   // DC (reg ISIG(0) = 0)
        }
    }

    // ================= inverse four-step (forward FFT of conj spectrum) =================
    fft32t<1>(v);
    twmult<1>(v, A1);
    __syncwarp();             // WAR: forward transpose reads done in all lanes
    #pragma unroll
    for (int p = 0; p < 32; p++) tbw[33 * SIG(p) + lane] = v[MIDX(1, p)];
    __syncwarp();
    #pragma unroll
    for (int n2 = 0; n2 < 32; n2++) v[n2] = tbw[33 * lane + n2];
    fft32t<0>(v);             // reg q: time sample n = 32*SIG(q) + lane (x1024, conj)

    // ---- Hann window + FUSED overlap-add, guarded (40 predicated atomics) ----
    const float* wp = wint + lane;
    float* op = out + nOff + base0 + lane;
    #pragma unroll
    for (int h = 0; h < 40; h++) {
        float acc;
        if (h < 8)
            acc = v[ISIG(h)].x * wp[32 * h];
        else if (h < 32)
            acc = fmaf(v[ISIG(h)].x, wp[32 * h],
                       -v[ISIG(h - 8)].y * wp[32 * (h - 8)]);
        else
            acc = -v[ISIG(h - 8)].y * wp[32 * (h - 8)];
        int s = base0 + 32 * h + lane;
        if ((unsigned)s < (unsigned)LOUT)
            atomicAdd(&op[32 * h], acc);
    }
}

extern "C" void kernel_launch(void* const* d_in, const int* in_sizes, int n_in,
                              void* d_out, int out_size)
{
    const float* fb    = (const float*)d_in[0];
    const float* noise = (const float*)d_in[1];
    float* out = (float*)d_out;

    cudaMemsetAsync(out, 0, (size_t)out_size * sizeof(float));

    // all 501 pairs, 4 warps/block
    filtered_noise_kernel<<<dim3((NPAIR + 3) / 4, 16), 128>>>(fb, noise, out);
}

// round 13
// speedup vs baseline: 1.1182x; 1.1168x over previous
#include <cuda_runtime.h>

#define HOP    256
#define NB     128
#define TFR    1001
#define LOUT   256000
#define NPAIR  501            // ceil(1001/2)

// edge staging: raw noise where valid, 0.5f in margins (-> 0 after fmaf(x,2,-1))
__device__ float g_lo[16][1280];   // samples [-512, 768)   for pair 0
__device__ float g_hi[16][1792];   // samples [254976, 256768) for pairs 499/500

// ---- packed f32x2 ops (Blackwell) ----
__device__ __forceinline__ float2 padd(float2 a, float2 b) {
    float2 r;
    asm("add.rn.f32x2 %0, %1, %2;"
        : "=l"(reinterpret_cast<unsigned long long&>(r))
        : "l"(reinterpret_cast<unsigned long long&>(a)),
          "l"(reinterpret_cast<unsigned long long&>(b)));
    return r;
}
__device__ __forceinline__ float2 psub(float2 a, float2 b) {
    float2 r;
    asm("sub.rn.f32x2 %0, %1, %2;"
        : "=l"(reinterpret_cast<unsigned long long&>(r))
        : "l"(reinterpret_cast<unsigned long long&>(a)),
          "l"(reinterpret_cast<unsigned long long&>(b)));
    return r;
}
__device__ __forceinline__ float2 cmul(float2 a, float2 b) {
    return make_float2(fmaf(a.x, b.x, -a.y * b.y), fmaf(a.x, b.y, a.y * b.x));
}

// Output permutation of the local 32-pt DIF FFT (radix 4,4,2):
// position p = 8a + 2b + c  holds bin  k = a + 4b + 16c
__host__ __device__ constexpr int SIG(int p)  { return (p >> 3) + 4 * ((p >> 1) & 3) + 16 * (p & 1); }
__host__ __device__ constexpr int ISIG(int k) { return 8 * (k & 3) + 2 * ((k >> 2) & 3) + (k >> 4); }
__host__ __device__ constexpr int MIDX(int P, int i) { return P ? ISIG(i) : i; }

// W_32^k constants, k = 0..21 : (cos(2pi k/32), -sin(2pi k/32))
__device__ __constant__ const float W32R[22] = {
    1.0f, 0.98078528f, 0.92387953f, 0.83146961f, 0.70710678f, 0.55557023f,
    0.38268343f, 0.19509032f, 0.0f, -0.19509032f, -0.38268343f, -0.55557023f,
    -0.70710678f, -0.83146961f, -0.92387953f, -0.98078528f, -1.0f,
    -0.98078528f, -0.92387953f, -0.83146961f, -0.70710678f, -0.55557023f };
__device__ __constant__ const float W32I[22] = {
    0.0f, -0.19509032f, -0.38268343f, -0.55557023f, -0.70710678f, -0.83146961f,
    -0.92387953f, -0.98078528f, -1.0f, -0.98078528f, -0.92387953f, -0.83146961f,
    -0.70710678f, -0.55557023f, -0.38268343f, -0.19509032f, 0.0f,
    0.19509032f, 0.38268343f, 0.55557023f, 0.70710678f, 0.83146961f };

__device__ __forceinline__ void bf_dif3(float2& a, float2& b, float2& c, float2& d,
                                        float2 w1, float2 w2, float2 w3) {
    float2 t0 = padd(a, c), t1 = psub(a, c), t2 = padd(b, d);
    float2 t3 = make_float2(b.y - d.y, d.x - b.x);   // -i*(b-d)
    a = padd(t0, t2);
    float2 o1 = padd(t1, t3), o2 = psub(t0, t2), o3 = psub(t1, t3);
    b = cmul(o1, w1); c = cmul(o2, w2); d = cmul(o3, w3);
}
__device__ __forceinline__ void bf_dif_nt(float2& a, float2& b, float2& c, float2& d) {
    float2 t0 = padd(a, c), t1 = psub(a, c), t2 = padd(b, d);
    float2 t3 = make_float2(b.y - d.y, d.x - b.x);
    a = padd(t0, t2); b = padd(t1, t3); c = psub(t0, t2); d = psub(t1, t3);
}

// In-place 32-pt DIF FFT with compile-time register remap P.
template<int P>
__device__ __forceinline__ void fft32t(float2 v[32]) {
    bf_dif_nt(v[MIDX(P,0)], v[MIDX(P,8)], v[MIDX(P,16)], v[MIDX(P,24)]);
    #pragma unroll
    for (int i = 1; i < 8; i++)
        bf_dif3(v[MIDX(P,i)], v[MIDX(P,i+8)], v[MIDX(P,i+16)], v[MIDX(P,i+24)],
                make_float2(W32R[i], W32I[i]),
                make_float2(W32R[2 * i], W32I[2 * i]),
                make_float2(W32R[3 * i], W32I[3 * i]));
    #pragma unroll
    for (int blk = 0; blk < 4; blk++) {
        const int s = 8 * blk;
        bf_dif_nt(v[MIDX(P,s)], v[MIDX(P,s+2)], v[MIDX(P,s+4)], v[MIDX(P,s+6)]);
        bf_dif3(v[MIDX(P,s+1)], v[MIDX(P,s+3)], v[MIDX(P,s+5)], v[MIDX(P,s+7)],
                make_float2(W32R[4], W32I[4]),
                make_float2(W32R[8], W32I[8]),
                make_float2(W32R[12], W32I[12]));
    }
    #pragma unroll
    for (int u = 0; u < 16; u++) {
        float2 a = v[MIDX(P,2*u)], b = v[MIDX(P,2*u+1)];
        v[MIDX(P,2*u)]   = padd(a, b);
        v[MIDX(P,2*u+1)] = psub(a, b);
    }
}

// Multiply logical slot ISIG(m) (bin k1=m) by W_1024^{lane*m}; base A1 = W_1024^lane.
template<int P>
__device__ __forceinline__ void twmult(float2 v[32], float2 A1) {
    float2 A2 = cmul(A1, A1);
    float2 A4 = cmul(A2, A2);
    float2 B8  = cmul(A4, A4);
    float2 B16 = cmul(B8, B8);
    float2 B24 = cmul(B16, B8);
    v[MIDX(P,ISIG(8))]  = cmul(v[MIDX(P,ISIG(8))],  B8);
    v[MIDX(P,ISIG(16))] = cmul(v[MIDX(P,ISIG(16))], B16);
    v[MIDX(P,ISIG(24))] = cmul(v[MIDX(P,ISIG(24))], B24);
    float2 A = A1;
    #pragma unroll
    for (int d = 1; d < 8; d++) {
        v[MIDX(P,ISIG(d))]      = cmul(v[MIDX(P,ISIG(d))],      A);
        v[MIDX(P,ISIG(8 + d))]  = cmul(v[MIDX(P,ISIG(8 + d))],  cmul(B8,  A));
        v[MIDX(P,ISIG(16 + d))] = cmul(v[MIDX(P,ISIG(16 + d))], cmul(B16, A));
        v[MIDX(P,ISIG(24 + d))] = cmul(v[MIDX(P,ISIG(24 + d))], cmul(B24, A));
        if (d < 7) A = cmul(A, A1);
    }
}

// W[k] = gp*Zk + gm*conj(Zm); returns conj(W)
__device__ __forceinline__ float2 combW(float g0, float g1, float2 Zk, float2 Zm) {
    float gp = 0.5f * (g0 + g1), gm = 0.5f * (g0 - g1);
    return make_float2(fmaf(gp, Zk.x, gm * Zm.x),
                       fmaf(-gp, Zk.y, gm * Zm.y));
}

__device__ __forceinline__ float2 shfl2(float2 v, int src) {
    float2 r;
    r.x = __shfl_sync(0xffffffffu, v.x, src);
    r.y = __shfl_sync(0xffffffffu, v.y, src);
    return r;
}

// Fill edge staging buffers. 16 blocks (one per batch), 256 threads.
__global__ void edge_fill(const float* __restrict__ noise)
{
    const int b = blockIdx.x;
    const int t = threadIdx.x;
    const float* np = noise + (size_t)b * LOUT;
    #pragma unroll
    for (int i = t; i < 1280; i += 256)
        g_lo[b][i] = (i >= 512) ? np[i - 512] : 0.5f;
    #pragma unroll
    for (int i = t; i < 1792; i += 256) {
        int s = 254976 + i;            // base0 of pair 499
        g_hi[b][i] = (s < LOUT) ? np[s] : 0.5f;
    }
}

// Single kernel, all 501 pairs. Unguarded loads (edge pairs read staging bufs);
// guards only in the (post-pressure-peak) epilogue for edge warps.
__global__ void __launch_bounds__(128, 5)
filtered_noise_kernel(const float* __restrict__ fb,     // (16,1,128,1001)
                      const float* __restrict__ noise,  // (16,1,256000)
                      float* __restrict__ out)          // (16,1,256000)
{
    __shared__ float2 tb[4][33 * 32];   // per-warp transpose buffer (33-stride pad)
    __shared__ float2 FP[4][NB];        // per-warp (g0,g1) band gains
    __shared__ float  wint[1024];       // Hann * (1/1024)

    const int tid  = threadIdx.x;
    const int wid  = tid >> 5;
    const int lane = tid & 31;
    const int b    = blockIdx.y;
    const int pr   = blockIdx.x * 4 + wid;

    #pragma unroll
    for (int idx = tid; idx < 1024; idx += 128)
        wint[idx] = 0.5f * (1.0f - cospif((float)(2 * idx) * (1.0f / 1023.0f)))
                  * (1.0f / 1024.0f);
    __syncthreads();
    if (pr >= NPAIR) return;

    const int  t0 = 2 * pr;
    const bool v1 = (t0 + 1) < TFR;    // uniform; guards only the fb gain load

    float2* FPw = FP[wid];
    #pragma unroll
    for (int u = lane; u < NB; u += 32) {
        float g0 = fb[(b * NB + u) * TFR + t0];
        float g1 = v1 ? fb[(b * NB + u) * TFR + t0 + 1] : 0.0f;
        FPw[u] = make_float2(g0, g1);
    }

    float2* tbw = tb[wid];
    const int    base0 = t0 * HOP - 512;
    const size_t nOff  = (size_t)b * LOUT;
    float2 A1;
    {
        float sn, cs;
        sincospif(-(float)lane * (1.0f / 512.0f), &sn, &cs);
        A1 = make_float2(cs, sn);
    }

    // ---- uniform per-warp source select; all loads unguarded ----
    const float* np;
    if (pr == 0)          np = &g_lo[b][0];
    else if (pr >= 499)   np = &g_hi[b][(pr - 499) * 512];
    else                  np = noise + nOff + base0;
    np += lane;

    float2 v[32];
    #pragma unroll
    for (int n1 = 0; n1 < 32; n1++) {
        float xa = np[32 * n1];
        float xb = np[32 * n1 + HOP];
        v[n1] = make_float2(fmaf(xa, 2.0f, -1.0f), fmaf(xb, 2.0f, -1.0f));
    }

    // ================= forward four-step FFT =================
    fft32t<0>(v);             // over n1; reg p holds k1 = SIG(p)
    twmult<0>(v, A1);         // *= W_1024^{lane * k1}
    #pragma unroll
    for (int p = 0; p < 32; p++) tbw[33 * SIG(p) + lane] = v[p];
    __syncwarp();
    #pragma unroll
    for (int n2 = 0; n2 < 32; n2++) v[n2] = tbw[33 * lane + n2];
    fft32t<0>(v);             // reg q holds bin k = 32*SIG(q) + lane

    // ================= spectral combine, IN PLACE (bin-indexed regs) =================
    {
        const int pl = (32 - lane) & 31;
        #pragma unroll
        for (int sq = 0; sq < 16; sq++) {
            const int q = ISIG(sq), tq = ISIG(31 - sq);
            float2 pq  = shfl2(v[tq], pl);   // partner value for bin at reg q
            float2 ptq = shfl2(v[q],  pl);   // partner value for bin at reg tq
            if (lane != 0) {
                float2 gq  = FPw[(32 * sq + lane - 1) >> 2];
                float2 gtq = FPw[(32 * sq + 31 - lane) >> 2];
                float2 nq  = combW(gq.x,  gq.y,  v[q],  pq);
                float2 ntq = combW(gtq.x, gtq.y, v[tq], ptq);
                v[q]  = nq;
                v[tq] = ntq;
            }
        }
        if (lane == 0) {
            #pragma unroll
            for (int sq = 1; sq < 16; sq++) {
                const int qa = ISIG(sq), qb = ISIG(32 - sq);
                float2 A = v[qa], B = v[qb];
                float2 g = FPw[(32 * sq - 1) >> 2];
                v[qa] = combW(g.x, g.y, A, B);
                v[qb] = combW(g.x, g.y, B, A);
            }
            float2 g512 = FPw[127];
            v[ISIG(16)] = combW(g512.x, g512.y, v[ISIG(16)], v[ISIG(16)]);
            v[0] = make_float2(0.0f, 0.0f);   // DC (reg ISIG(0) = 0)
        }
    }

    // ================= inverse four-step (forward FFT of conj spectrum) =================
    fft32t<1>(v);
    twmult<1>(v, A1);
    __syncwarp();             // WAR: forward transpose reads done in all lanes
    #pragma unroll
    for (int p = 0; p < 32; p++) tbw[33 * SIG(p) + lane] = v[MIDX(1, p)];
    __syncwarp();
    #pragma unroll
    for (int n2 = 0; n2 < 32; n2++) v[n2] = tbw[33 * lane + n2];
    fft32t<0>(v);             // reg q: time sample n = 32*SIG(q) + lane (x1024, conj)

    // ---- Hann window + FUSED overlap-add (40 atomics) ----
    const float* wp = wint + lane;
    float* op = out + nOff + base0 + lane;
    const bool edge = (pr == 0) || (pr >= 499);
    if (!edge) {
        #pragma unroll
        for (int h = 0; h < 40; h++) {
            float acc;
            if (h < 8)
                acc = v[ISIG(h)].x * wp[32 * h];
            else if (h < 32)
                acc = fmaf(v[ISIG(h)].x, wp[32 * h],
                           -v[ISIG(h - 8)].y * wp[32 * (h - 8)]);
            else
                acc = -v[ISIG(h - 8)].y * wp[32 * (h - 8)];
            atomicAdd(&op[32 * h], acc);
        }
    } else {
        #pragma unroll
        for (int h = 0; h < 40; h++) {
            float acc;
            if (h < 8)
                acc = v[ISIG(h)].x * wp[32 * h];
            else if (h < 32)
                acc = fmaf(v[ISIG(h)].x, wp[32 * h],
                           -v[ISIG(h - 8)].y * wp[32 * (h - 8)]);
            else
                acc = -v[ISIG(h - 8)].y * wp[32 * (h - 8)];
            int s = base0 + 32 * h + lane;
            if ((unsigned)s < (unsigned)LOUT)
                atomicAdd(&op[32 * h], acc);
        }
    }
}

extern "C" void kernel_launch(void* const* d_in, const int* in_sizes, int n_in,
                              void* d_out, int out_size)
{
    const float* fb    = (const float*)d_in[0];
    const float* noise = (const float*)d_in[1];
    float* out = (float*)d_out;

    cudaMemsetAsync(out, 0, (size_t)out_size * sizeof(float));
    edge_fill<<<16, 256>>>(noise);

    // all 501 pairs, 4 warps/block
    filtered_noise_kernel<<<dim3((NPAIR + 3) / 4, 16), 128>>>(fb, noise, out);
}

// round 14
// speedup vs baseline: 1.2035x; 1.0763x over previous
#include <cuda_runtime.h>

#define HOP    256
#define NB     128
#define TFR    1001
#define LOUT   256000
#define NPAIR  501            // ceil(1001/2)

// edge staging: raw noise where valid, 0.5f in margins (-> 0 after fmaf(x,2,-1))
__device__ float g_lo[16][1280];   // samples [-512, 768)   for pair 0
__device__ float g_hi[16][1792];   // samples [254976, 256768) for pairs 499/500

// ---- packed f32x2 ops (Blackwell) ----
__device__ __forceinline__ float2 padd(float2 a, float2 b) {
    float2 r;
    asm("add.rn.f32x2 %0, %1, %2;"
        : "=l"(reinterpret_cast<unsigned long long&>(r))
        : "l"(reinterpret_cast<unsigned long long&>(a)),
          "l"(reinterpret_cast<unsigned long long&>(b)));
    return r;
}
__device__ __forceinline__ float2 psub(float2 a, float2 b) {
    float2 r;
    asm("sub.rn.f32x2 %0, %1, %2;"
        : "=l"(reinterpret_cast<unsigned long long&>(r))
        : "l"(reinterpret_cast<unsigned long long&>(a)),
          "l"(reinterpret_cast<unsigned long long&>(b)));
    return r;
}
__device__ __forceinline__ float2 cmul(float2 a, float2 b) {
    return make_float2(fmaf(a.x, b.x, -a.y * b.y), fmaf(a.x, b.y, a.y * b.x));
}

// Output permutation of the local 32-pt DIF FFT (radix 4,4,2):
// position p = 8a + 2b + c  holds bin  k = a + 4b + 16c
__host__ __device__ constexpr int SIG(int p)  { return (p >> 3) + 4 * ((p >> 1) & 3) + 16 * (p & 1); }
__host__ __device__ constexpr int ISIG(int k) { return 8 * (k & 3) + 2 * ((k >> 2) & 3) + (k >> 4); }
__host__ __device__ constexpr int MIDX(int P, int i) { return P ? ISIG(i) : i; }

// W_32^k as COMPILE-TIME LITERALS (constexpr fn -> folded into FFMA immediates;
// Blackwell has no cbank operands, so __constant__ arrays would emit LDC).
__host__ __device__ constexpr float W32R_f(int k) {
    constexpr float t[22] = {
        1.0f, 0.98078528f, 0.92387953f, 0.83146961f, 0.70710678f, 0.55557023f,
        0.38268343f, 0.19509032f, 0.0f, -0.19509032f, -0.38268343f, -0.55557023f,
        -0.70710678f, -0.83146961f, -0.92387953f, -0.98078528f, -1.0f,
        -0.98078528f, -0.92387953f, -0.83146961f, -0.70710678f, -0.55557023f };
    return t[k];
}
__host__ __device__ constexpr float W32I_f(int k) {
    constexpr float t[22] = {
        0.0f, -0.19509032f, -0.38268343f, -0.55557023f, -0.70710678f, -0.83146961f,
        -0.92387953f, -0.98078528f, -1.0f, -0.98078528f, -0.92387953f, -0.83146961f,
        -0.70710678f, -0.55557023f, -0.38268343f, -0.19509032f, 0.0f,
        0.19509032f, 0.38268343f, 0.55557023f, 0.70710678f, 0.83146961f };
    return t[k];
}

__device__ __forceinline__ void bf_dif3(float2& a, float2& b, float2& c, float2& d,
                                        float2 w1, float2 w2, float2 w3) {
    float2 t0 = padd(a, c), t1 = psub(a, c), t2 = padd(b, d);
    float2 t3 = make_float2(b.y - d.y, d.x - b.x);   // -i*(b-d)
    a = padd(t0, t2);
    float2 o1 = padd(t1, t3), o2 = psub(t0, t2), o3 = psub(t1, t3);
    b = cmul(o1, w1); c = cmul(o2, w2); d = cmul(o3, w3);
}
__device__ __forceinline__ void bf_dif_nt(float2& a, float2& b, float2& c, float2& d) {
    float2 t0 = padd(a, c), t1 = psub(a, c), t2 = padd(b, d);
    float2 t3 = make_float2(b.y - d.y, d.x - b.x);
    a = padd(t0, t2); b = padd(t1, t3); c = psub(t0, t2); d = psub(t1, t3);
}

// In-place 32-pt DIF FFT with compile-time register remap P.
template<int P>
__device__ __forceinline__ void fft32t(float2 v[32]) {
    bf_dif_nt(v[MIDX(P,0)], v[MIDX(P,8)], v[MIDX(P,16)], v[MIDX(P,24)]);
    #pragma unroll
    for (int i = 1; i < 8; i++)
        bf_dif3(v[MIDX(P,i)], v[MIDX(P,i+8)], v[MIDX(P,i+16)], v[MIDX(P,i+24)],
                make_float2(W32R_f(i), W32I_f(i)),
                make_float2(W32R_f(2 * i), W32I_f(2 * i)),
                make_float2(W32R_f(3 * i), W32I_f(3 * i)));
    #pragma unroll
    for (int blk = 0; blk < 4; blk++) {
        const int s = 8 * blk;
        bf_dif_nt(v[MIDX(P,s)], v[MIDX(P,s+2)], v[MIDX(P,s+4)], v[MIDX(P,s+6)]);
        bf_dif3(v[MIDX(P,s+1)], v[MIDX(P,s+3)], v[MIDX(P,s+5)], v[MIDX(P,s+7)],
                make_float2(W32R_f(4), W32I_f(4)),
                make_float2(W32R_f(8), W32I_f(8)),
                make_float2(W32R_f(12), W32I_f(12)));
    }
    #pragma unroll
    for (int u = 0; u < 16; u++) {
        float2 a = v[MIDX(P,2*u)], b = v[MIDX(P,2*u+1)];
        v[MIDX(P,2*u)]   = padd(a, b);
        v[MIDX(P,2*u+1)] = psub(a, b);
    }
}

// Multiply logical slot ISIG(m) (bin k1=m) by W_1024^{lane*m}; base A1 = W_1024^lane.
template<int P>
__device__ __forceinline__ void twmult(float2 v[32], float2 A1) {
    float2 A2 = cmul(A1, A1);
    float2 A4 = cmul(A2, A2);
    float2 B8  = cmul(A4, A4);
    float2 B16 = cmul(B8, B8);
    float2 B24 = cmul(B16, B8);
    v[MIDX(P,ISIG(8))]  = cmul(v[MIDX(P,ISIG(8))],  B8);
    v[MIDX(P,ISIG(16))] = cmul(v[MIDX(P,ISIG(16))], B16);
    v[MIDX(P,ISIG(24))] = cmul(v[MIDX(P,ISIG(24))], B24);
    float2 A = A1;
    #pragma unroll
    for (int d = 1; d < 8; d++) {
        v[MIDX(P,ISIG(d))]      = cmul(v[MIDX(P,ISIG(d))],      A);
        v[MIDX(P,ISIG(8 + d))]  = cmul(v[MIDX(P,ISIG(8 + d))],  cmul(B8,  A));
        v[MIDX(P,ISIG(16 + d))] = cmul(v[MIDX(P,ISIG(16 + d))], cmul(B16, A));
        v[MIDX(P,ISIG(24 + d))] = cmul(v[MIDX(P,ISIG(24 + d))], cmul(B24, A));
        if (d < 7) A = cmul(A, A1);
    }
}

// gains pre-folded: W[k] = gp*Zk + gm*conj(Zm); returns conj(W)
__device__ __forceinline__ float2 combW(float gp, float gm, float2 Zk, float2 Zm) {
    return make_float2(fmaf(gp, Zk.x, gm * Zm.x),
                       fmaf(-gp, Zk.y, gm * Zm.y));
}

__device__ __forceinline__ float2 shfl2(float2 v, int src) {
    float2 r;
    r.x = __shfl_sync(0xffffffffu, v.x, src);
    r.y = __shfl_sync(0xffffffffu, v.y, src);
    return r;
}

// Fill edge staging buffers. 16 blocks (one per batch), 256 threads.
__global__ void edge_fill(const float* __restrict__ noise)
{
    const int b = blockIdx.x;
    const int t = threadIdx.x;
    const float* np = noise + (size_t)b * LOUT;
    #pragma unroll
    for (int i = t; i < 1280; i += 256)
        g_lo[b][i] = (i >= 512) ? np[i - 512] : 0.5f;
    #pragma unroll
    for (int i = t; i < 1792; i += 256) {
        int s = 254976 + i;            // base0 of pair 499
        g_hi[b][i] = (s < LOUT) ? np[s] : 0.5f;
    }
}

// Single kernel, all 501 pairs. Unguarded loads (edge pairs read staging bufs).
__global__ void __launch_bounds__(128, 4)
filtered_noise_kernel(const float* __restrict__ fb,     // (16,1,128,1001)
                      const float* __restrict__ noise,  // (16,1,256000)
                      float* __restrict__ out)          // (16,1,256000)
{
    __shared__ float2 tb[4][33 * 32];   // per-warp transpose buffer (33-stride pad)
    __shared__ float2 FP[4][NB];        // per-warp (gp, gm) folded band gains
    __shared__ float  wint[1024];       // Hann * (1/1024)

    const int tid  = threadIdx.x;
    const int wid  = tid >> 5;
    const int lane = tid & 31;
    const int b    = blockIdx.y;
    const int pr   = blockIdx.x * 4 + wid;

    #pragma unroll
    for (int idx = tid; idx < 1024; idx += 128)
        wint[idx] = 0.5f * (1.0f - cospif((float)(2 * idx) * (1.0f / 1023.0f)))
                  * (1.0f / 1024.0f);
    __syncthreads();
    if (pr >= NPAIR) return;

    const int  t0 = 2 * pr;
    const bool v1 = (t0 + 1) < TFR;    // uniform; guards only the fb gain load

    float2* FPw = FP[wid];
    #pragma unroll
    for (int u = lane; u < NB; u += 32) {
        float g0 = fb[(b * NB + u) * TFR + t0];
        float g1 = v1 ? fb[(b * NB + u) * TFR + t0 + 1] : 0.0f;
        FPw[u] = make_float2(0.5f * (g0 + g1), 0.5f * (g0 - g1));
    }

    float2* tbw = tb[wid];
    const int    base0 = t0 * HOP - 512;
    const size_t nOff  = (size_t)b * LOUT;
    float2 A1;
    {
        float sn, cs;
        sincospif(-(float)lane * (1.0f / 512.0f), &sn, &cs);
        A1 = make_float2(cs, sn);
    }

    // ---- uniform per-warp source select; all loads unguarded ----
    const float* np;
    if (pr == 0)          np = &g_lo[b][0];
    else if (pr >= 499)   np = &g_hi[b][(pr - 499) * 512];
    else                  np = noise + nOff + base0;
    np += lane;

    float2 v[32];
    #pragma unroll
    for (int n1 = 0; n1 < 32; n1++) {
        float xa = np[32 * n1];
        float xb = np[32 * n1 + HOP];
        v[n1] = make_float2(fmaf(xa, 2.0f, -1.0f), fmaf(xb, 2.0f, -1.0f));
    }

    // ================= forward four-step FFT =================
    fft32t<0>(v);             // over n1; reg p holds k1 = SIG(p)
    twmult<0>(v, A1);         // *= W_1024^{lane * k1}
    #pragma unroll
    for (int p = 0; p < 32; p++) tbw[33 * SIG(p) + lane] = v[p];
    __syncwarp();
    #pragma unroll
    for (int n2 = 0; n2 < 32; n2++) v[n2] = tbw[33 * lane + n2];
    fft32t<0>(v);             // reg q holds bin k = 32*SIG(q) + lane

    // ================= spectral combine, IN PLACE (bin-indexed regs) =================
    {
        const int pl = (32 - lane) & 31;
        #pragma unroll
        for (int sq = 0; sq < 16; sq++) {
            const int q = ISIG(sq), tq = ISIG(31 - sq);
            float2 pq  = shfl2(v[tq], pl);   // partner value for bin at reg q
            float2 ptq = shfl2(v[q],  pl);   // partner value for bin at reg tq
            if (lane != 0) {
                float2 gq  = FPw[(32 * sq + lane - 1) >> 2];
                float2 gtq = FPw[(32 * sq + 31 - lane) >> 2];
                float2 nq  = combW(gq.x,  gq.y,  v[q],  pq);
                float2 ntq = combW(gtq.x, gtq.y, v[tq], ptq);
                v[q]  = nq;
                v[tq] = ntq;
            }
        }
        if (lane == 0) {
            #pragma unroll
            for (int sq = 1; sq < 16; sq++) {
                const int qa = ISIG(sq), qb = ISIG(32 - sq);
                float2 A = v[qa], B = v[qb];
                float2 g = FPw[(32 * sq - 1) >> 2];
                v[qa] = combW(g.x, g.y, A, B);
                v[qb] = combW(g.x, g.y, B, A);
            }
            float2 g512 = FPw[127];
            v[ISIG(16)] = combW(g512.x, g512.y, v[ISIG(16)], v[ISIG(16)]);
            v[0] = make_float2(0.0f, 0.0f);   // DC (reg ISIG(0) = 0)
        }
    }

    // ================= inverse four-step (forward FFT of conj spectrum) =================
    fft32t<1>(v);
    twmult<1>(v, A1);
    __syncwarp();             // WAR: forward transpose reads done in all lanes
    #pragma unroll
    for (int p = 0; p < 32; p++) tbw[33 * SIG(p) + lane] = v[MIDX(1, p)];
    __syncwarp();
    #pragma unroll
    for (int n2 = 0; n2 < 32; n2++) v[n2] = tbw[33 * lane + n2];
    fft32t<0>(v);             // reg q: time sample n = 32*SIG(q) + lane (x1024, conj)

    // ---- Hann window + FUSED overlap-add (40 atomics) ----
    const float* wp = wint + lane;
    float* op = out + nOff + base0 + lane;
    const bool edge = (pr == 0) || (pr >= 499);
    if (!edge) {
        #pragma unroll
        for (int h = 0; h < 40; h++) {
            float acc;
            if (h < 8)
                acc = v[ISIG(h)].x * wp[32 * h];
            else if (h < 32)
                acc = fmaf(v[ISIG(h)].x, wp[32 * h],
                           -v[ISIG(h - 8)].y * wp[32 * (h - 8)]);
            else
                acc = -v[ISIG(h - 8)].y * wp[32 * (h - 8)];
            atomicAdd(&op[32 * h], acc);
        }
    } else {
        #pragma unroll
        for (int h = 0; h < 40; h++) {
            float acc;
            if (h < 8)
                acc = v[ISIG(h)].x * wp[32 * h];
            else if (h < 32)
                acc = fmaf(v[ISIG(h)].x, wp[32 * h],
                           -v[ISIG(h - 8)].y * wp[32 * (h - 8)]);
            else
                acc = -v[ISIG(h - 8)].y * wp[32 * (h - 8)];
            int s = base0 + 32 * h + lane;
            if ((unsigned)s < (unsigned)LOUT)
                atomicAdd(&op[32 * h], acc);
        }
    }
}

extern "C" void kernel_launch(void* const* d_in, const int* in_sizes, int n_in,
                              void* d_out, int out_size)
{
    const float* fb    = (const float*)d_in[0];
    const float* noise = (const float*)d_in[1];
    float* out = (float*)d_out;

    cudaMemsetAsync(out, 0, (size_t)out_size * sizeof(float));
    edge_fill<<<16, 256>>>(noise);

    // all 501 pairs, 4 warps/block
    filtered_noise_kernel<<<dim3((NPAIR + 3) / 4, 16), 128>>>(fb, noise, out);
}